// round 13
// baseline (speedup 1.0000x reference)
#include <cuda_runtime.h>
#include <cuda_fp16.h>
#include <cstdint>

#define BATCH  4
#define NPT    4096
#define CDIM   256
#define DDIM   128
#define NGROUP 50
#define BN     (BATCH*NPT)

#define OFF_SOFT    0
#define OFF_LOGITS  819200
#define OFF_SIM     1638400
#define OFF_CONF    68747264
#define OFF_CONFLOG 68763648

// Scratch (device globals: allocation-free)
__device__ __half2 g_FsimH[BN*DDIM/2];     // fp16 Fsim, row-major k-pairs
__device__ __half2 g_XH[BN*CDIM/2];        // fp16 X, row-major k-pairs
__device__ __half2 g_WH[3*DDIM*CDIM/2];    // [head][n][kw] = {W[2kw][n], W[2kw+1][n]}
__device__ float   g_r[BN];

#define CHSTR 1026   // words per k16-chunk in smem frag layout (1024 + 2 pad)
#define GTILE 128
#define TTSTR 132
#define NTILES 528                              // triangular tiles per batch
#define HEADS_CTAS 256                          // 128 head0 + 128 head2
#define GSMEM_WORDS (2*8*CHSTR)                 // 16416 words = 65664 B
#define GSMEM_BYTES (GSMEM_WORDS*4)

__device__ __forceinline__ void mma_f16(float c[4],
                                        uint32_t a0, uint32_t a1, uint32_t a2, uint32_t a3,
                                        uint32_t b0, uint32_t b1) {
    asm volatile(
        "mma.sync.aligned.m16n8k16.row.col.f32.f16.f16.f32 "
        "{%0,%1,%2,%3}, {%4,%5,%6,%7}, {%8,%9}, {%0,%1,%2,%3};"
        : "+f"(c[0]), "+f"(c[1]), "+f"(c[2]), "+f"(c[3])
        : "r"(a0), "r"(a1), "r"(a2), "r"(a3), "r"(b0), "r"(b1));
}

// ---------------------------------------------------------------------------
// prep kernels: pack X and W into fp16 layouts
// ---------------------------------------------------------------------------
__global__ __launch_bounds__(256) void prep_x(const float* __restrict__ X)
{
    int i = (blockIdx.x*256 + threadIdx.x)*4;
    float4 v = *(const float4*)(X + i);
    g_XH[(i>>1) + 0] = __floats2half2_rn(v.x, v.y);
    g_XH[(i>>1) + 1] = __floats2half2_rn(v.z, v.w);
}

__global__ __launch_bounds__(256) void prep_w(const float* __restrict__ W0,
                                              const float* __restrict__ W1,
                                              const float* __restrict__ W2)
{
    int idx = blockIdx.x*256 + threadIdx.x;     // 0..49151
    int head = idx >> 14;
    int r    = idx & 16383;
    int n    = r >> 7;
    int kw   = r & 127;
    const float* W = (head == 0) ? W0 : (head == 1) ? W1 : W2;
    g_WH[idx] = __floats2half2_rn(W[(2*kw)*DDIM + n], W[(2*kw+1)*DDIM + n]);
}

// ---------------------------------------------------------------------------
// Shared mainloop for head GEMMs (F = X @ W): 128x128 tile, K=256, fp16 mma.
// Writes accumulators into c[2][8][4]. Buffers sA/sB provided by caller.
// ---------------------------------------------------------------------------
__device__ __forceinline__
void head_mainloop(uint32_t* sA, uint32_t* sB, const uint4* WB,
                   int m0, int tid, int wm, int wn, int gID, int tg,
                   float c[2][8][4])
{
    const uint4* XA = (const uint4*)g_XH;
    for (int st = 0; st < 4; ++st) {
        __syncthreads();
        #pragma unroll
        for (int it = 0; it < 4; ++it) {
            int u   = tid + it*256;
            int row = u >> 3;
            int g4  = u & 7;
            int chl = g4 >> 1, kw4 = g4 & 1;
            uint4 va = XA[(size_t)(m0+row)*32 + st*8 + g4];
            uint4 vb = WB[(size_t)row*32 + st*8 + g4];
            int base = chl*CHSTR + row*8 + kw4;
            sA[base+0] = va.x; sA[base+2] = va.y; sA[base+4] = va.z; sA[base+6] = va.w;
            sB[base+0] = vb.x; sB[base+2] = vb.y; sB[base+4] = vb.z; sB[base+6] = vb.w;
        }
        __syncthreads();

        #pragma unroll
        for (int chl = 0; chl < 4; ++chl) {
            uint32_t a[2][4];
            #pragma unroll
            for (int mt = 0; mt < 2; ++mt) {
                int r0 = wm*32 + mt*16 + gID;
                int ad = chl*CHSTR + r0*8 + tg*2;
                uint2 p0 = *(const uint2*)(sA + ad);
                uint2 p1 = *(const uint2*)(sA + ad + 64);
                a[mt][0] = p0.x; a[mt][2] = p0.y;
                a[mt][1] = p1.x; a[mt][3] = p1.y;
            }
            #pragma unroll
            for (int nt = 0; nt < 8; ++nt) {
                int n  = wn*64 + nt*8 + gID;
                int bd = chl*CHSTR + n*8 + tg*2;
                uint2 bp = *(const uint2*)(sB + bd);
                mma_f16(c[0][nt], a[0][0], a[0][1], a[0][2], a[0][3], bp.x, bp.y);
                mma_f16(c[1][nt], a[1][0], a[1][1], a[1][2], a[1][3], bp.x, bp.y);
            }
        }
    }
    __syncthreads();
}

// ---------------------------------------------------------------------------
// heads_sim: head 1 only (Fsim fp16 + r).  Grid: BN/128.  MUST precede gram.
// ---------------------------------------------------------------------------
__global__ __launch_bounds__(256)
void heads_sim(const float* __restrict__ bias1)
{
    __shared__ __align__(16) uint32_t smem_u[8320];
    __shared__ float sRed[128];

    uint32_t* sA = smem_u;
    uint32_t* sB = smem_u + 4104;
    float*    Ts = (float*)smem_u;

    const int m0   = blockIdx.x * 128;
    const int tid  = threadIdx.x;
    const int lane = tid & 31;
    const int gID  = lane >> 2;
    const int tg   = lane & 3;
    const int wm   = (tid >> 5) & 3;
    const int wn   = tid >> 7;

    float c[2][8][4];
    #pragma unroll
    for (int mt = 0; mt < 2; ++mt)
        #pragma unroll
        for (int nt = 0; nt < 8; ++nt)
            #pragma unroll
            for (int rr = 0; rr < 4; ++rr) c[mt][nt][rr] = 0.f;

    head_mainloop(sA, sB, (const uint4*)g_WH + 4096, m0, tid, wm, wn, gID, tg, c);

    const int row = tid & 127;
    const int kh  = tid >> 7;
    float rs = 0.f;

    #pragma unroll
    for (int h = 0; h < 2; ++h) {
        if (wn == h) {
            #pragma unroll
            for (int mt = 0; mt < 2; ++mt) {
                int r0 = wm*32 + mt*16 + gID;
                #pragma unroll
                for (int nt = 0; nt < 8; ++nt) {
                    int c0l = nt*8 + tg*2;
                    int gc  = h*64 + c0l;
                    float b0 = bias1[gc], b1 = bias1[gc+1];
                    Ts[ r0   *65 + c0l    ] = c[mt][nt][0] + b0;
                    Ts[ r0   *65 + c0l + 1] = c[mt][nt][1] + b1;
                    Ts[(r0+8)*65 + c0l    ] = c[mt][nt][2] + b0;
                    Ts[(r0+8)*65 + c0l + 1] = c[mt][nt][3] + b1;
                }
            }
        }
        __syncthreads();

        #pragma unroll
        for (int it = 0; it < 16; ++it) {
            int u  = tid + it*256;
            int r2 = u >> 5;
            int c2 = u & 31;
            __half2 hv = __floats2half2_rn(Ts[r2*65 + c2*2], Ts[r2*65 + c2*2 + 1]);
            g_FsimH[(size_t)(m0+r2)*64 + h*32 + c2] = hv;
        }
        #pragma unroll 8
        for (int kl = 0; kl < 32; ++kl) {
            float v = Ts[row*65 + kh*32 + kl];
            float f = __half2float(__float2half_rn(v));
            rs += f*f;
        }
        __syncthreads();
    }

    if (kh == 1) sRed[row] = rs;
    __syncthreads();
    if (kh == 0) g_r[m0 + row] = rs + sRed[row];
}

// ---------------------------------------------------------------------------
// fat_kernel: blocks [0,128) head0, [128,256) head2, [256,2368) gram tiles.
// Heads first -> they start in wave 1 and hide under gram's store stream.
// All smem aliased into one dynamic buffer (65.7 KB).
// ---------------------------------------------------------------------------
__global__ __launch_bounds__(256)
void fat_kernel(float* __restrict__ out,
                const float* __restrict__ bias0, const float* __restrict__ bias2,
                const float* __restrict__ Wseg,  const float* __restrict__ bseg,
                const float* __restrict__ Wcl,   const float* __restrict__ bcl,
                float* __restrict__ o_soft, float* __restrict__ o_logits,
                float* __restrict__ o_conf, float* __restrict__ o_conflog)
{
    extern __shared__ __align__(16) uint32_t dsm[];
    __shared__ float rm_s[GTILE], rn_s[GTILE];

    const int bx   = blockIdx.x;
    const int tid  = threadIdx.x;
    const int lane = tid & 31;
    const int w    = tid >> 5;
    const int gID  = lane >> 2;
    const int tg   = lane & 3;
    const int wm   = w & 3;
    const int wn   = w >> 2;

    if (bx < HEADS_CTAS) {
        // ================= heads branch (head 0 or 2) =================
        const int head = (bx >> 7) ? 2 : 0;
        const int m0   = (bx & 127) * 128;
        const float* bias = head ? bias2 : bias0;

        uint32_t* sA  = dsm;
        uint32_t* sB  = dsm + 4104;
        float*    Ts  = (float*)dsm;              // words 0..8319
        float*    red = (float*)dsm;
        float*    sW   = (float*)(dsm + 8320);    // 3328 words
        float*    sWcl = (float*)(dsm + 11648);   // 128
        float*    sRed = (float*)(dsm + 11776);   // 128

        if (head == 2 && tid < 128) sWcl[tid] = Wcl[tid];

        float c[2][8][4];
        #pragma unroll
        for (int mt = 0; mt < 2; ++mt)
            #pragma unroll
            for (int nt = 0; nt < 8; ++nt)
                #pragma unroll
                for (int rr = 0; rr < 4; ++rr) c[mt][nt][rr] = 0.f;

        head_mainloop(sA, sB, (const uint4*)g_WH + head*4096,
                      m0, tid, wm, wn, gID, tg, c);

        const int row = tid & 127;
        const int kh  = tid >> 7;

        float accS[50];
        float cd = 0.f;
        if (head == 0) {
            #pragma unroll
            for (int g = 0; g < 50; ++g) accS[g] = 0.f;
        }

        #pragma unroll
        for (int h = 0; h < 2; ++h) {
            if (wn == h) {
                #pragma unroll
                for (int mt = 0; mt < 2; ++mt) {
                    int r0 = wm*32 + mt*16 + gID;
                    #pragma unroll
                    for (int nt = 0; nt < 8; ++nt) {
                        int c0l = nt*8 + tg*2;
                        int gc  = h*64 + c0l;
                        float b0 = bias[gc], b1 = bias[gc+1];
                        Ts[ r0   *65 + c0l    ] = c[mt][nt][0] + b0;
                        Ts[ r0   *65 + c0l + 1] = c[mt][nt][1] + b1;
                        Ts[(r0+8)*65 + c0l    ] = c[mt][nt][2] + b0;
                        Ts[(r0+8)*65 + c0l + 1] = c[mt][nt][3] + b1;
                    }
                }
            }
            if (head == 0) {
                for (int i2 = tid; i2 < 64*NGROUP; i2 += 256) {
                    int kl = i2 / NGROUP, g = i2 - kl*NGROUP;
                    sW[kl*52 + g] = Wseg[(size_t)(h*64 + kl)*NGROUP + g];
                }
            }
            __syncthreads();

            if (head == 0) {
                #pragma unroll 4
                for (int kl = 0; kl < 32; ++kl) {
                    float fv = Ts[row*65 + kh*32 + kl];
                    const float4* wr = (const float4*)&sW[(kh*32 + kl)*52];
                    #pragma unroll
                    for (int g4 = 0; g4 < 12; ++g4) {
                        float4 ww = wr[g4];
                        accS[g4*4+0] += fv*ww.x; accS[g4*4+1] += fv*ww.y;
                        accS[g4*4+2] += fv*ww.z; accS[g4*4+3] += fv*ww.w;
                    }
                    float2 wt = *(const float2*)&sW[(kh*32 + kl)*52 + 48];
                    accS[48] += fv*wt.x; accS[49] += fv*wt.y;
                }
            } else {
                #pragma unroll 8
                for (int kl = 0; kl < 32; ++kl)
                    cd += Ts[row*65 + kh*32 + kl] * sWcl[h*64 + kh*32 + kl];
            }
            __syncthreads();
        }

        if (head == 0) {
            if (kh == 1) {
                #pragma unroll
                for (int g = 0; g < 50; ++g) red[row*52 + g] = accS[g];
            }
            __syncthreads();
            float mx = -1e30f, inv = 0.f;
            if (kh == 0) {
                #pragma unroll
                for (int g = 0; g < 50; ++g) {
                    accS[g] += red[row*52 + g] + bseg[g];
                    mx = fmaxf(mx, accS[g]);
                }
                float s = 0.f;
                #pragma unroll
                for (int g = 0; g < 50; ++g) s += expf(accS[g] - mx);
                inv = 1.0f / s;
            }
            __syncthreads();
            if (kh == 0) {
                #pragma unroll
                for (int g = 0; g < 50; ++g) red[row*52 + g] = accS[g];
            }
            __syncthreads();
            for (int i2 = tid; i2 < 128*NGROUP; i2 += 256) {
                int r2 = i2 / NGROUP, g = i2 - r2*NGROUP;
                o_logits[(size_t)m0*NGROUP + i2] = red[r2*52 + g];
            }
            __syncthreads();
            if (kh == 0) {
                #pragma unroll
                for (int g = 0; g < 50; ++g) red[row*52 + g] = expf(accS[g] - mx)*inv;
            }
            __syncthreads();
            for (int i2 = tid; i2 < 128*NGROUP; i2 += 256) {
                int r2 = i2 / NGROUP, g = i2 - r2*NGROUP;
                o_soft[(size_t)m0*NGROUP + i2] = red[r2*52 + g];
            }
        } else {
            if (kh == 1) sRed[row] = cd;
            __syncthreads();
            if (kh == 0) {
                float cl = cd + sRed[row] + bcl[0];
                o_conflog[m0 + row] = cl;
                o_conf[m0 + row]    = 1.0f / (1.0f + expf(-cl));
            }
        }
        return;
    }

    // ================= gram branch =================
    const int idx = bx - HEADS_CTAS;
    const int b   = idx / NTILES;
    const int t   = idx - b*NTILES;

    uint32_t* sA = dsm;
    uint32_t* sB = dsm + 8*CHSTR;
    float*    Tt = (float*)dsm;

    int j = (int)((sqrtf(8.0f*(float)t + 1.0f) - 1.0f) * 0.5f);
    while ((j+1)*(j+2)/2 <= t) ++j;
    while (j*(j+1)/2 > t)      --j;
    const int i  = t - j*(j+1)/2;       // i <= j
    const int m0 = i*GTILE, n0 = j*GTILE;
    const bool diag = (i == j);

    const uint4* FH = (const uint4*)g_FsimH + (size_t)b*NPT*16;
    const float* rb = g_r + b*NPT;

    if (tid < GTILE) {
        rm_s[tid] = rb[m0 + tid];
        rn_s[tid] = rb[n0 + tid];
    }

    // full-K load, conflict-free (banks: chl*2+kw4+row*8 mod 32 all distinct)
    {
        const int row = tid >> 3;
        const int g4h = tid & 7;
        #pragma unroll
        for (int half = 0; half < 2; ++half) {
            int g4  = half*8 + g4h;
            int chl = g4 >> 1, kw4 = g4 & 1;
            #pragma unroll
            for (int it = 0; it < 4; ++it) {
                int r2 = row + it*32;
                int base = chl*CHSTR + r2*8 + kw4;
                uint4 va = FH[(size_t)(m0+r2)*16 + g4];
                sA[base+0] = va.x; sA[base+2] = va.y; sA[base+4] = va.z; sA[base+6] = va.w;
                if (!diag) {
                    uint4 vb = FH[(size_t)(n0+r2)*16 + g4];
                    sB[base+0] = vb.x; sB[base+2] = vb.y; sB[base+4] = vb.z; sB[base+6] = vb.w;
                }
            }
        }
    }
    __syncthreads();

    const uint32_t* sBr = diag ? sA : sB;

    float c[2][8][4];
    #pragma unroll
    for (int mt = 0; mt < 2; ++mt)
        #pragma unroll
        for (int nt = 0; nt < 8; ++nt)
            #pragma unroll
            for (int rr = 0; rr < 4; ++rr) c[mt][nt][rr] = 0.f;

    #pragma unroll
    for (int chl = 0; chl < 8; ++chl) {
        uint32_t a[2][4];
        #pragma unroll
        for (int mt = 0; mt < 2; ++mt) {
            int r0 = wm*32 + mt*16 + gID;
            int ad = chl*CHSTR + r0*8 + tg*2;
            uint2 p0 = *(const uint2*)(sA + ad);
            uint2 p1 = *(const uint2*)(sA + ad + 64);
            a[mt][0] = p0.x; a[mt][2] = p0.y;
            a[mt][1] = p1.x; a[mt][3] = p1.y;
        }
        #pragma unroll
        for (int nt = 0; nt < 8; ++nt) {
            int n  = wn*64 + nt*8 + gID;
            int bd = chl*CHSTR + n*8 + tg*2;
            uint2 bp = *(const uint2*)(sBr + bd);
            mma_f16(c[0][nt], a[0][0], a[0][1], a[0][2], a[0][3], bp.x, bp.y);
            mma_f16(c[1][nt], a[1][0], a[1][1], a[1][2], a[1][3], bp.x, bp.y);
        }
    }

    const int rA = wm*32 + gID;
    #pragma unroll
    for (int mt = 0; mt < 2; ++mt) {
        int r0 = rA + mt*16;
        float rm0 = rm_s[r0], rm1 = rm_s[r0 + 8];
        #pragma unroll
        for (int nt = 0; nt < 8; ++nt) {
            int gc0 = wn*64 + nt*8 + tg*2;
            float rn0 = rn_s[gc0], rn1 = rn_s[gc0 + 1];
            float d00 = fmaxf(10.0f*(rm0 + rn0 - 2.0f*c[mt][nt][0]), 0.0f);
            float d01 = fmaxf(10.0f*(rm0 + rn1 - 2.0f*c[mt][nt][1]), 0.0f);
            float d10 = fmaxf(10.0f*(rm1 + rn0 - 2.0f*c[mt][nt][2]), 0.0f);
            float d11 = fmaxf(10.0f*(rm1 + rn1 - 2.0f*c[mt][nt][3]), 0.0f);
            if (diag) {
                if (r0   == gc0)   d00 = 0.0f;
                if (r0   == gc0+1) d01 = 0.0f;
                if (r0+8 == gc0)   d10 = 0.0f;
                if (r0+8 == gc0+1) d11 = 0.0f;
            }
            c[mt][nt][0] = d00; c[mt][nt][1] = d01;
            c[mt][nt][2] = d10; c[mt][nt][3] = d11;
        }
    }

    const size_t base = (size_t)b * NPT * NPT;

    {
        float* orow = out + base + (size_t)m0*NPT + n0;
        #pragma unroll
        for (int mt = 0; mt < 2; ++mt) {
            int r0 = rA + mt*16;
            #pragma unroll
            for (int nt = 0; nt < 8; ++nt) {
                int gc0 = wn*64 + nt*8 + tg*2;
                __stcs((float2*)&orow[(size_t)r0*NPT + gc0],
                       make_float2(c[mt][nt][0], c[mt][nt][1]));
                __stcs((float2*)&orow[(size_t)(r0+8)*NPT + gc0],
                       make_float2(c[mt][nt][2], c[mt][nt][3]));
            }
        }
    }

    if (!diag) {
        #pragma unroll
        for (int h = 0; h < 2; ++h) {
            __syncthreads();
            if (wn == h) {
                #pragma unroll
                for (int mt = 0; mt < 2; ++mt) {
                    int r0 = rA + mt*16;
                    #pragma unroll
                    for (int nt = 0; nt < 8; ++nt) {
                        int cl = nt*8 + tg*2;
                        Tt[ cl   *TTSTR + r0    ] = c[mt][nt][0];
                        Tt[(cl+1)*TTSTR + r0    ] = c[mt][nt][1];
                        Tt[ cl   *TTSTR + r0 + 8] = c[mt][nt][2];
                        Tt[(cl+1)*TTSTR + r0 + 8] = c[mt][nt][3];
                    }
                }
            }
            __syncthreads();
            float* ocol = out + base + (size_t)(n0 + h*64)*NPT + m0;
            #pragma unroll
            for (int it = 0; it < 8; ++it) {
                int idx2 = tid + it*256;
                int cc  = idx2 >> 5;
                int f4  = idx2 & 31;
                float4 vv = *(float4*)&Tt[cc*TTSTR + f4*4];
                __stcs((float4*)&ocol[(size_t)cc*NPT + f4*4], vv);
            }
        }
    }
}

// ---------------------------------------------------------------------------
extern "C" void kernel_launch(void* const* d_in, const int* in_sizes, int n_in,
                              void* d_out, int out_size)
{
    const float* X     = (const float*)d_in[0];
    const float* Wsem  = (const float*)d_in[1];
    const float* bsem  = (const float*)d_in[2];
    const float* Wseg  = (const float*)d_in[3];
    const float* bseg  = (const float*)d_in[4];
    const float* Wsim  = (const float*)d_in[5];
    const float* bsim  = (const float*)d_in[6];
    const float* Wconf = (const float*)d_in[7];
    const float* bconf = (const float*)d_in[8];
    const float* Wcl   = (const float*)d_in[9];
    const float* bcl   = (const float*)d_in[10];

    float* out       = (float*)d_out;
    float* o_soft    = out + OFF_SOFT;
    float* o_logits  = out + OFF_LOGITS;
    float* o_sim     = out + OFF_SIM;
    float* o_conf    = out + OFF_CONF;
    float* o_conflog = out + OFF_CONFLOG;

    cudaFuncSetAttribute(fat_kernel, cudaFuncAttributeMaxDynamicSharedMemorySize,
                         GSMEM_BYTES);

    prep_x<<<BN*CDIM/1024, 256>>>(X);
    prep_w<<<192, 256>>>(Wsem, Wsim, Wconf);

    heads_sim<<<BN/128, 256>>>(bsim);

    fat_kernel<<<HEADS_CTAS + NTILES*BATCH, 256, GSMEM_BYTES>>>(
        o_sim, bsem, bconf, Wseg, bseg, Wcl, bcl,
        o_soft, o_logits, o_conf, o_conflog);
}

// round 15
// speedup vs baseline: 1.7845x; 1.7845x over previous
#include <cuda_runtime.h>
#include <cuda_fp16.h>
#include <cstdint>

#define BATCH  4
#define NPT    4096
#define CDIM   256
#define DDIM   128
#define NGROUP 50
#define BN     (BATCH*NPT)

#define OFF_SOFT    0
#define OFF_LOGITS  819200
#define OFF_SIM     1638400
#define OFF_CONF    68747264
#define OFF_CONFLOG 68763648

// Scratch (device globals: allocation-free)
__device__ __half2 g_FsimH[BN*DDIM/2];     // fp16 Fsim, row-major k-pairs
__device__ __half2 g_XH[BN*CDIM/2];        // fp16 X, row-major k-pairs
__device__ __half2 g_WH[3*DDIM*CDIM/2];    // [head][n][kw] = {W[2kw][n], W[2kw+1][n]}
__device__ float   g_r[BN];

#define CHSTR 1026   // words per k16-chunk in smem frag layout (1024 + 2 pad)
#define GTILE 128
#define TTSTR 132
#define NTILES 528                              // triangular tiles per batch
#define HEADS_CTAS 256                          // 128 head0 + 128 head2
// dynamic smem: max(gram 16416, heads Ts0+Ts1+sW+sWcl+sRed = 23552) words
#define GSMEM_WORDS 23552
#define GSMEM_BYTES (GSMEM_WORDS*4)

__device__ __forceinline__ void mma_f16(float c[4],
                                        uint32_t a0, uint32_t a1, uint32_t a2, uint32_t a3,
                                        uint32_t b0, uint32_t b1) {
    asm volatile(
        "mma.sync.aligned.m16n8k16.row.col.f32.f16.f16.f32 "
        "{%0,%1,%2,%3}, {%4,%5,%6,%7}, {%8,%9}, {%0,%1,%2,%3};"
        : "+f"(c[0]), "+f"(c[1]), "+f"(c[2]), "+f"(c[3])
        : "r"(a0), "r"(a1), "r"(a2), "r"(a3), "r"(b0), "r"(b1));
}

// ---------------------------------------------------------------------------
// prep kernels: pack X and W into fp16 layouts
// ---------------------------------------------------------------------------
__global__ __launch_bounds__(256) void prep_x(const float* __restrict__ X)
{
    int i = (blockIdx.x*256 + threadIdx.x)*4;
    float4 v = *(const float4*)(X + i);
    g_XH[(i>>1) + 0] = __floats2half2_rn(v.x, v.y);
    g_XH[(i>>1) + 1] = __floats2half2_rn(v.z, v.w);
}

__global__ __launch_bounds__(256) void prep_w(const float* __restrict__ W0,
                                              const float* __restrict__ W1,
                                              const float* __restrict__ W2)
{
    int idx = blockIdx.x*256 + threadIdx.x;     // 0..49151
    int head = idx >> 14;
    int r    = idx & 16383;
    int n    = r >> 7;
    int kw   = r & 127;
    const float* W = (head == 0) ? W0 : (head == 1) ? W1 : W2;
    g_WH[idx] = __floats2half2_rn(W[(2*kw)*DDIM + n], W[(2*kw+1)*DDIM + n]);
}

// ---------------------------------------------------------------------------
// Shared mainloop for head GEMMs (F = X @ W): 128x128 tile, K=256, fp16 mma.
// ---------------------------------------------------------------------------
__device__ __forceinline__
void head_mainloop(uint32_t* sA, uint32_t* sB, const uint4* WB,
                   int m0, int tid, int wm, int wn, int gID, int tg,
                   float c[2][8][4])
{
    const uint4* XA = (const uint4*)g_XH;
    for (int st = 0; st < 4; ++st) {
        __syncthreads();
        #pragma unroll
        for (int it = 0; it < 4; ++it) {
            int u   = tid + it*256;
            int row = u >> 3;
            int g4  = u & 7;
            int chl = g4 >> 1, kw4 = g4 & 1;
            uint4 va = XA[(size_t)(m0+row)*32 + st*8 + g4];
            uint4 vb = WB[(size_t)row*32 + st*8 + g4];
            int base = chl*CHSTR + row*8 + kw4;
            sA[base+0] = va.x; sA[base+2] = va.y; sA[base+4] = va.z; sA[base+6] = va.w;
            sB[base+0] = vb.x; sB[base+2] = vb.y; sB[base+4] = vb.z; sB[base+6] = vb.w;
        }
        __syncthreads();

        #pragma unroll
        for (int chl = 0; chl < 4; ++chl) {
            uint32_t a[2][4];
            #pragma unroll
            for (int mt = 0; mt < 2; ++mt) {
                int r0 = wm*32 + mt*16 + gID;
                int ad = chl*CHSTR + r0*8 + tg*2;
                uint2 p0 = *(const uint2*)(sA + ad);
                uint2 p1 = *(const uint2*)(sA + ad + 64);
                a[mt][0] = p0.x; a[mt][2] = p0.y;
                a[mt][1] = p1.x; a[mt][3] = p1.y;
            }
            #pragma unroll
            for (int nt = 0; nt < 8; ++nt) {
                int n  = wn*64 + nt*8 + gID;
                int bd = chl*CHSTR + n*8 + tg*2;
                uint2 bp = *(const uint2*)(sB + bd);
                mma_f16(c[0][nt], a[0][0], a[0][1], a[0][2], a[0][3], bp.x, bp.y);
                mma_f16(c[1][nt], a[1][0], a[1][1], a[1][2], a[1][3], bp.x, bp.y);
            }
        }
    }
    __syncthreads();
}

// ---------------------------------------------------------------------------
// heads_sim: head 1 only (Fsim fp16 + r).  Grid: BN/128.  MUST precede gram.
// (R13 version — per-half staging, verified correct.)
// ---------------------------------------------------------------------------
__global__ __launch_bounds__(256)
void heads_sim(const float* __restrict__ bias1)
{
    __shared__ __align__(16) uint32_t smem_u[8320];
    __shared__ float sRed[128];

    uint32_t* sA = smem_u;
    uint32_t* sB = smem_u + 4104;
    float*    Ts = (float*)smem_u;

    const int m0   = blockIdx.x * 128;
    const int tid  = threadIdx.x;
    const int lane = tid & 31;
    const int gID  = lane >> 2;
    const int tg   = lane & 3;
    const int wm   = (tid >> 5) & 3;
    const int wn   = tid >> 7;

    float c[2][8][4];
    #pragma unroll
    for (int mt = 0; mt < 2; ++mt)
        #pragma unroll
        for (int nt = 0; nt < 8; ++nt)
            #pragma unroll
            for (int rr = 0; rr < 4; ++rr) c[mt][nt][rr] = 0.f;

    head_mainloop(sA, sB, (const uint4*)g_WH + 4096, m0, tid, wm, wn, gID, tg, c);

    const int row = tid & 127;
    const int kh  = tid >> 7;
    float rs = 0.f;

    #pragma unroll
    for (int h = 0; h < 2; ++h) {
        if (wn == h) {
            #pragma unroll
            for (int mt = 0; mt < 2; ++mt) {
                int r0 = wm*32 + mt*16 + gID;
                #pragma unroll
                for (int nt = 0; nt < 8; ++nt) {
                    int c0l = nt*8 + tg*2;
                    int gc  = h*64 + c0l;
                    float b0 = bias1[gc], b1 = bias1[gc+1];
                    Ts[ r0   *65 + c0l    ] = c[mt][nt][0] + b0;
                    Ts[ r0   *65 + c0l + 1] = c[mt][nt][1] + b1;
                    Ts[(r0+8)*65 + c0l    ] = c[mt][nt][2] + b0;
                    Ts[(r0+8)*65 + c0l + 1] = c[mt][nt][3] + b1;
                }
            }
        }
        __syncthreads();

        #pragma unroll
        for (int it = 0; it < 16; ++it) {
            int u  = tid + it*256;
            int r2 = u >> 5;
            int c2 = u & 31;
            __half2 hv = __floats2half2_rn(Ts[r2*65 + c2*2], Ts[r2*65 + c2*2 + 1]);
            g_FsimH[(size_t)(m0+r2)*64 + h*32 + c2] = hv;
        }
        #pragma unroll 8
        for (int kl = 0; kl < 32; ++kl) {
            float v = Ts[row*65 + kh*32 + kl];
            float f = __half2float(__float2half_rn(v));
            rs += f*f;
        }
        __syncthreads();
    }

    if (kh == 1) sRed[row] = rs;
    __syncthreads();
    if (kh == 0) g_r[m0 + row] = rs + sRed[row];
}

// ---------------------------------------------------------------------------
// fat_kernel: blocks [0,128) head0, [128,256) head2, [256,2368) gram tiles.
// Heads: stage both halves into Ts0/Ts1 (each [128][65], local col index) in
// ONE pass -> accumulators die before seg/conf accumulate (disjoint phases).
// __launch_bounds__(256,2) keeps gram at 2 CTAs/SM.
// ---------------------------------------------------------------------------
__global__ __launch_bounds__(256, 2)
void fat_kernel(float* __restrict__ out,
                const float* __restrict__ bias0, const float* __restrict__ bias2,
                const float* __restrict__ Wseg,  const float* __restrict__ bseg,
                const float* __restrict__ Wcl,   const float* __restrict__ bcl,
                float* __restrict__ o_soft, float* __restrict__ o_logits,
                float* __restrict__ o_conf, float* __restrict__ o_conflog)
{
    extern __shared__ __align__(16) uint32_t dsm[];
    __shared__ float rm_s[GTILE], rn_s[GTILE];

    const int bx   = blockIdx.x;
    const int tid  = threadIdx.x;
    const int lane = tid & 31;
    const int w    = tid >> 5;
    const int gID  = lane >> 2;
    const int tg   = lane & 3;
    const int wm   = w & 3;
    const int wn   = w >> 2;

    if (bx < HEADS_CTAS) {
        // ================= heads branch (head 0 or 2) =================
        const int head = (bx >> 7) ? 2 : 0;
        const int m0   = (bx & 127) * 128;
        const float* bias = head ? bias2 : bias0;

        uint32_t* sA   = dsm;                     // mainloop (words 0..8207)
        uint32_t* sB   = dsm + 4104;
        float*    Ts0  = (float*)dsm;             // [128][65] half 0 (0..8319)
        float*    Ts1  = (float*)(dsm + 8320);    // [128][65] half 1
        float*    red  = (float*)dsm;             // aliases Ts0 after it's dead
        float*    sW   = (float*)(dsm + 16640);   // [128][52] = 6656 words
        float*    sWcl = (float*)(dsm + 23296);   // 128
        float*    sRed = (float*)(dsm + 23424);   // 128

        {
            float c[2][8][4];
            #pragma unroll
            for (int mt = 0; mt < 2; ++mt)
                #pragma unroll
                for (int nt = 0; nt < 8; ++nt)
                    #pragma unroll
                    for (int rr = 0; rr < 4; ++rr) c[mt][nt][rr] = 0.f;

            head_mainloop(sA, sB, (const uint4*)g_WH + head*4096,
                          m0, tid, wm, wn, gID, tg, c);

            // stage BOTH halves in one pass: warp wn writes its own buffer,
            // LOCAL column index (proven conflict-free stride-65 layout).
            float* Tsh = wn ? Ts1 : Ts0;
            #pragma unroll
            for (int mt = 0; mt < 2; ++mt) {
                int r0 = wm*32 + mt*16 + gID;
                #pragma unroll
                for (int nt = 0; nt < 8; ++nt) {
                    int c0l = nt*8 + tg*2;          // local col 0..63
                    int gc  = wn*64 + c0l;          // global col
                    float b0 = bias[gc], b1 = bias[gc+1];
                    Tsh[ r0   *65 + c0l    ] = c[mt][nt][0] + b0;
                    Tsh[ r0   *65 + c0l + 1] = c[mt][nt][1] + b1;
                    Tsh[(r0+8)*65 + c0l    ] = c[mt][nt][2] + b0;
                    Tsh[(r0+8)*65 + c0l + 1] = c[mt][nt][3] + b1;
                }
            }
        }   // accumulators dead here — register phases disjoint

        // load weights (disjoint smem region), then sync once
        if (head == 0) {
            for (int i2 = tid; i2 < 128*NGROUP; i2 += 256) {
                int kl = i2 / NGROUP, g = i2 - kl*NGROUP;
                sW[kl*52 + g] = Wseg[i2];
            }
        } else if (tid < 128) {
            sWcl[tid] = Wcl[tid];
        }
        __syncthreads();

        const int row = tid & 127;
        const int kh  = tid >> 7;             // k-half [kh*64, kh*64+64)
        const float* Tsrc = kh ? Ts1 : Ts0;   // local k index within half

        if (head == 0) {
            float accS[50];
            #pragma unroll
            for (int g = 0; g < 50; ++g) accS[g] = 0.f;

            #pragma unroll 2
            for (int kl = 0; kl < 64; ++kl) {
                float fv = Tsrc[row*65 + kl];
                const float4* wr = (const float4*)&sW[(kh*64 + kl)*52];
                #pragma unroll
                for (int g4 = 0; g4 < 12; ++g4) {
                    float4 ww = wr[g4];
                    accS[g4*4+0] += fv*ww.x; accS[g4*4+1] += fv*ww.y;
                    accS[g4*4+2] += fv*ww.z; accS[g4*4+3] += fv*ww.w;
                }
                float2 wt = *(const float2*)&sW[(kh*64 + kl)*52 + 48];
                accS[48] += fv*wt.x; accS[49] += fv*wt.y;
            }
            __syncthreads();            // Ts0/Ts1 dead; red may alias Ts0

            if (kh == 1) {
                #pragma unroll
                for (int g = 0; g < 50; ++g) red[row*52 + g] = accS[g];
            }
            __syncthreads();
            float mx = -1e30f, inv = 0.f;
            if (kh == 0) {
                #pragma unroll
                for (int g = 0; g < 50; ++g) {
                    accS[g] += red[row*52 + g] + bseg[g];
                    mx = fmaxf(mx, accS[g]);
                }
                float s = 0.f;
                #pragma unroll
                for (int g = 0; g < 50; ++g) s += expf(accS[g] - mx);
                inv = 1.0f / s;
            }
            __syncthreads();
            if (kh == 0) {
                #pragma unroll
                for (int g = 0; g < 50; ++g) red[row*52 + g] = accS[g];
            }
            __syncthreads();
            for (int i2 = tid; i2 < 128*NGROUP; i2 += 256) {
                int r2 = i2 / NGROUP, g = i2 - r2*NGROUP;
                o_logits[(size_t)m0*NGROUP + i2] = red[r2*52 + g];
            }
            __syncthreads();
            if (kh == 0) {
                #pragma unroll
                for (int g = 0; g < 50; ++g) red[row*52 + g] = expf(accS[g] - mx)*inv;
            }
            __syncthreads();
            for (int i2 = tid; i2 < 128*NGROUP; i2 += 256) {
                int r2 = i2 / NGROUP, g = i2 - r2*NGROUP;
                o_soft[(size_t)m0*NGROUP + i2] = red[r2*52 + g];
            }
        } else {
            float cd = 0.f;
            #pragma unroll 8
            for (int kl = 0; kl < 64; ++kl)
                cd += Tsrc[row*65 + kl] * sWcl[kh*64 + kl];
            __syncthreads();
            if (kh == 1) sRed[row] = cd;
            __syncthreads();
            if (kh == 0) {
                float cl = cd + sRed[row] + bcl[0];
                o_conflog[m0 + row] = cl;
                o_conf[m0 + row]    = 1.0f / (1.0f + expf(-cl));
            }
        }
        return;
    }

    // ================= gram branch =================
    const int idx = bx - HEADS_CTAS;
    const int b   = idx / NTILES;
    const int t   = idx - b*NTILES;

    uint32_t* sA = dsm;
    uint32_t* sB = dsm + 8*CHSTR;
    float*    Tt = (float*)dsm;

    int j = (int)((sqrtf(8.0f*(float)t + 1.0f) - 1.0f) * 0.5f);
    while ((j+1)*(j+2)/2 <= t) ++j;
    while (j*(j+1)/2 > t)      --j;
    const int i  = t - j*(j+1)/2;       // i <= j
    const int m0 = i*GTILE, n0 = j*GTILE;
    const bool diag = (i == j);

    const uint4* FH = (const uint4*)g_FsimH + (size_t)b*NPT*16;
    const float* rb = g_r + b*NPT;

    if (tid < GTILE) {
        rm_s[tid] = rb[m0 + tid];
        rn_s[tid] = rb[n0 + tid];
    }

    // full-K load, conflict-free (banks: chl*2+kw4+row*8 mod 32 all distinct)
    {
        const int row = tid >> 3;
        const int g4h = tid & 7;
        #pragma unroll
        for (int half = 0; half < 2; ++half) {
            int g4  = half*8 + g4h;
            int chl = g4 >> 1, kw4 = g4 & 1;
            #pragma unroll
            for (int it = 0; it < 4; ++it) {
                int r2 = row + it*32;
                int base = chl*CHSTR + r2*8 + kw4;
                uint4 va = FH[(size_t)(m0+r2)*16 + g4];
                sA[base+0] = va.x; sA[base+2] = va.y; sA[base+4] = va.z; sA[base+6] = va.w;
                if (!diag) {
                    uint4 vb = FH[(size_t)(n0+r2)*16 + g4];
                    sB[base+0] = vb.x; sB[base+2] = vb.y; sB[base+4] = vb.z; sB[base+6] = vb.w;
                }
            }
        }
    }
    __syncthreads();

    const uint32_t* sBr = diag ? sA : sB;

    float c[2][8][4];
    #pragma unroll
    for (int mt = 0; mt < 2; ++mt)
        #pragma unroll
        for (int nt = 0; nt < 8; ++nt)
            #pragma unroll
            for (int rr = 0; rr < 4; ++rr) c[mt][nt][rr] = 0.f;

    #pragma unroll
    for (int chl = 0; chl < 8; ++chl) {
        uint32_t a[2][4];
        #pragma unroll
        for (int mt = 0; mt < 2; ++mt) {
            int r0 = wm*32 + mt*16 + gID;
            int ad = chl*CHSTR + r0*8 + tg*2;
            uint2 p0 = *(const uint2*)(sA + ad);
            uint2 p1 = *(const uint2*)(sA + ad + 64);
            a[mt][0] = p0.x; a[mt][2] = p0.y;
            a[mt][1] = p1.x; a[mt][3] = p1.y;
        }
        #pragma unroll
        for (int nt = 0; nt < 8; ++nt) {
            int n  = wn*64 + nt*8 + gID;
            int bd = chl*CHSTR + n*8 + tg*2;
            uint2 bp = *(const uint2*)(sBr + bd);
            mma_f16(c[0][nt], a[0][0], a[0][1], a[0][2], a[0][3], bp.x, bp.y);
            mma_f16(c[1][nt], a[1][0], a[1][1], a[1][2], a[1][3], bp.x, bp.y);
        }
    }

    const int rA = wm*32 + gID;
    #pragma unroll
    for (int mt = 0; mt < 2; ++mt) {
        int r0 = rA + mt*16;
        float rm0 = rm_s[r0], rm1 = rm_s[r0 + 8];
        #pragma unroll
        for (int nt = 0; nt < 8; ++nt) {
            int gc0 = wn*64 + nt*8 + tg*2;
            float rn0 = rn_s[gc0], rn1 = rn_s[gc0 + 1];
            float d00 = fmaxf(10.0f*(rm0 + rn0 - 2.0f*c[mt][nt][0]), 0.0f);
            float d01 = fmaxf(10.0f*(rm0 + rn1 - 2.0f*c[mt][nt][1]), 0.0f);
            float d10 = fmaxf(10.0f*(rm1 + rn0 - 2.0f*c[mt][nt][2]), 0.0f);
            float d11 = fmaxf(10.0f*(rm1 + rn1 - 2.0f*c[mt][nt][3]), 0.0f);
            if (diag) {
                if (r0   == gc0)   d00 = 0.0f;
                if (r0   == gc0+1) d01 = 0.0f;
                if (r0+8 == gc0)   d10 = 0.0f;
                if (r0+8 == gc0+1) d11 = 0.0f;
            }
            c[mt][nt][0] = d00; c[mt][nt][1] = d01;
            c[mt][nt][2] = d10; c[mt][nt][3] = d11;
        }
    }

    const size_t base = (size_t)b * NPT * NPT;

    {
        float* orow = out + base + (size_t)m0*NPT + n0;
        #pragma unroll
        for (int mt = 0; mt < 2; ++mt) {
            int r0 = rA + mt*16;
            #pragma unroll
            for (int nt = 0; nt < 8; ++nt) {
                int gc0 = wn*64 + nt*8 + tg*2;
                __stcs((float2*)&orow[(size_t)r0*NPT + gc0],
                       make_float2(c[mt][nt][0], c[mt][nt][1]));
                __stcs((float2*)&orow[(size_t)(r0+8)*NPT + gc0],
                       make_float2(c[mt][nt][2], c[mt][nt][3]));
            }
        }
    }

    if (!diag) {
        #pragma unroll
        for (int h = 0; h < 2; ++h) {
            __syncthreads();
            if (wn == h) {
                #pragma unroll
                for (int mt = 0; mt < 2; ++mt) {
                    int r0 = rA + mt*16;
                    #pragma unroll
                    for (int nt = 0; nt < 8; ++nt) {
                        int cl = nt*8 + tg*2;
                        Tt[ cl   *TTSTR + r0    ] = c[mt][nt][0];
                        Tt[(cl+1)*TTSTR + r0    ] = c[mt][nt][1];
                        Tt[ cl   *TTSTR + r0 + 8] = c[mt][nt][2];
                        Tt[(cl+1)*TTSTR + r0 + 8] = c[mt][nt][3];
                    }
                }
            }
            __syncthreads();
            float* ocol = out + base + (size_t)(n0 + h*64)*NPT + m0;
            #pragma unroll
            for (int it = 0; it < 8; ++it) {
                int idx2 = tid + it*256;
                int cc  = idx2 >> 5;
                int f4  = idx2 & 31;
                float4 vv = *(float4*)&Tt[cc*TTSTR + f4*4];
                __stcs((float4*)&ocol[(size_t)cc*NPT + f4*4], vv);
            }
        }
    }
}

// ---------------------------------------------------------------------------
extern "C" void kernel_launch(void* const* d_in, const int* in_sizes, int n_in,
                              void* d_out, int out_size)
{
    const float* X     = (const float*)d_in[0];
    const float* Wsem  = (const float*)d_in[1];
    const float* bsem  = (const float*)d_in[2];
    const float* Wseg  = (const float*)d_in[3];
    const float* bseg  = (const float*)d_in[4];
    const float* Wsim  = (const float*)d_in[5];
    const float* bsim  = (const float*)d_in[6];
    const float* Wconf = (const float*)d_in[7];
    const float* bconf = (const float*)d_in[8];
    const float* Wcl   = (const float*)d_in[9];
    const float* bcl   = (const float*)d_in[10];

    float* out       = (float*)d_out;
    float* o_soft    = out + OFF_SOFT;
    float* o_logits  = out + OFF_LOGITS;
    float* o_sim     = out + OFF_SIM;
    float* o_conf    = out + OFF_CONF;
    float* o_conflog = out + OFF_CONFLOG;

    cudaFuncSetAttribute(fat_kernel, cudaFuncAttributeMaxDynamicSharedMemorySize,
                         GSMEM_BYTES);

    prep_x<<<BN*CDIM/1024, 256>>>(X);
    prep_w<<<192, 256>>>(Wsem, Wsim, Wconf);

    heads_sim<<<BN/128, 256>>>(bsim);

    fat_kernel<<<HEADS_CTAS + NTILES*BATCH, 256, GSMEM_BYTES>>>(
        o_sim, bsem, bconf, Wseg, bseg, Wcl, bcl,
        o_soft, o_logits, o_conf, o_conflog);
}